// round 2
// baseline (speedup 1.0000x reference)
#include <cuda_runtime.h>
#include <cstdint>
#include <cstddef>

// Problem constants (fixed by the dataset): B=16384, ND=20, D_G=D_H=64, D_EMB=16.
#define MAXB 16384
#define ND 20

// Scratch (static device globals; no allocation at runtime).
__device__ float g_pre [(size_t)ND * MAXB * 64];   // intermediate @ Wc1[:64] + bc1   (84 MB)
__device__ float g_ig  [(size_t)ND * MAXB * 16];   // intermediate @ We[:64]          (21 MB)
__device__ float g_gemm[(size_t)MAXB * 256];       // per-step: [0:64)=hproj, [64:256)=gh
__device__ float g_h   [(size_t)MAXB * 64];        // recurrent hidden state
__device__ float g_emb [(size_t)MAXB * 16];        // per-step GRU input embedding

__device__ __forceinline__ float sigmoidf_(float x) { return 1.f / (1.f + __expf(-x)); }

// ---------------------------------------------------------------------------
// init: h <- zo[-1] (zo is (1,B,64))
// ---------------------------------------------------------------------------
__global__ void copy_h_kernel(const float* __restrict__ zo, int n)
{
    int i = blockIdx.x * blockDim.x + threadIdx.x;
    if (i < n) g_h[i] = zo[i];
}

// ---------------------------------------------------------------------------
// C[m0:m0+64, n0:n0+64] = A[m0:m0+64, 0:64] @ W[0:64, n0:n0+64] (+ bias)
// A row-major lda=64. W row-major with ldW. 128 threads, 8x4 microtile.
// ---------------------------------------------------------------------------
__global__ void gemm64_kernel(const float* __restrict__ A,
                              const float* __restrict__ W, int ldW,
                              const float* __restrict__ bias,
                              float* __restrict__ C, int ldC)
{
    __shared__ float As[64][68];   // k-major, padded (68*4B = 17*16B -> float4-aligned rows)
    __shared__ float Ws[64][64];

    const int tid = threadIdx.x;
    const int m0  = blockIdx.x * 64;
    const int n0  = blockIdx.y * 64;

    // Load A tile (transpose to k-major)
    const float4* Ag = reinterpret_cast<const float4*>(A + (size_t)m0 * 64);
    #pragma unroll
    for (int i = 0; i < 8; i++) {
        int idx = tid + i * 128;           // 0..1023 float4s
        int r = idx >> 4, k4 = (idx & 15) << 2;
        float4 v = Ag[idx];
        As[k4 + 0][r] = v.x; As[k4 + 1][r] = v.y;
        As[k4 + 2][r] = v.z; As[k4 + 3][r] = v.w;
    }
    // Load W tile
    #pragma unroll
    for (int i = 0; i < 32; i++) {
        int idx = tid + i * 128;
        int k = idx >> 6, n = idx & 63;
        Ws[k][n] = W[(size_t)k * ldW + n0 + n];
    }
    __syncthreads();

    const int tx = tid & 15;    // n-group (4 cols)
    const int ty = tid >> 4;    // r-group (8 rows)

    float acc[8][4];
    #pragma unroll
    for (int i = 0; i < 8; i++)
        #pragma unroll
        for (int j = 0; j < 4; j++) acc[i][j] = 0.f;

    #pragma unroll
    for (int k = 0; k < 64; k++) {
        float4 w  = *reinterpret_cast<const float4*>(&Ws[k][tx << 2]);
        float4 a0 = *reinterpret_cast<const float4*>(&As[k][ty << 3]);
        float4 a1 = *reinterpret_cast<const float4*>(&As[k][(ty << 3) + 4]);
        float av[8] = {a0.x, a0.y, a0.z, a0.w, a1.x, a1.y, a1.z, a1.w};
        float wv[4] = {w.x, w.y, w.z, w.w};
        #pragma unroll
        for (int i = 0; i < 8; i++)
            #pragma unroll
            for (int j = 0; j < 4; j++)
                acc[i][j] = fmaf(av[i], wv[j], acc[i][j]);
    }

    float bv[4] = {0.f, 0.f, 0.f, 0.f};
    if (bias) {
        #pragma unroll
        for (int j = 0; j < 4; j++) bv[j] = bias[n0 + (tx << 2) + j];
    }
    #pragma unroll
    for (int i = 0; i < 8; i++) {
        float4 o;
        o.x = acc[i][0] + bv[0]; o.y = acc[i][1] + bv[1];
        o.z = acc[i][2] + bv[2]; o.w = acc[i][3] + bv[3];
        *reinterpret_cast<float4*>(&C[(size_t)(m0 + (ty << 3) + i) * ldC + n0 + (tx << 2)]) = o;
    }
}

// ---------------------------------------------------------------------------
// ig = A[M,64] @ W[64,16]  (W = first 64 rows of We), ldC = 16
// ---------------------------------------------------------------------------
__global__ void gemm16_kernel(const float* __restrict__ A,
                              const float* __restrict__ W,
                              float* __restrict__ C)
{
    __shared__ float As[64][68];
    __shared__ float Ws[64][16];

    const int tid = threadIdx.x;
    const int m0  = blockIdx.x * 64;

    const float4* Ag = reinterpret_cast<const float4*>(A + (size_t)m0 * 64);
    #pragma unroll
    for (int i = 0; i < 8; i++) {
        int idx = tid + i * 128;
        int r = idx >> 4, k4 = (idx & 15) << 2;
        float4 v = Ag[idx];
        As[k4 + 0][r] = v.x; As[k4 + 1][r] = v.y;
        As[k4 + 2][r] = v.z; As[k4 + 3][r] = v.w;
    }
    #pragma unroll
    for (int i = 0; i < 8; i++) {
        int idx = tid + i * 128;           // 0..1023
        int k = idx >> 4, n = idx & 15;
        Ws[k][n] = W[k * 16 + n];
    }
    __syncthreads();

    const int tx = tid & 3;     // n-group (4 cols)
    const int ty = tid >> 2;    // row-group (2 rows)

    float acc[2][4];
    #pragma unroll
    for (int i = 0; i < 2; i++)
        #pragma unroll
        for (int j = 0; j < 4; j++) acc[i][j] = 0.f;

    #pragma unroll
    for (int k = 0; k < 64; k++) {
        float4 w  = *reinterpret_cast<const float4*>(&Ws[k][tx << 2]);
        float a0 = As[k][(ty << 1) + 0];
        float a1 = As[k][(ty << 1) + 1];
        acc[0][0] = fmaf(a0, w.x, acc[0][0]); acc[0][1] = fmaf(a0, w.y, acc[0][1]);
        acc[0][2] = fmaf(a0, w.z, acc[0][2]); acc[0][3] = fmaf(a0, w.w, acc[0][3]);
        acc[1][0] = fmaf(a1, w.x, acc[1][0]); acc[1][1] = fmaf(a1, w.y, acc[1][1]);
        acc[1][2] = fmaf(a1, w.z, acc[1][2]); acc[1][3] = fmaf(a1, w.w, acc[1][3]);
    }
    #pragma unroll
    for (int i = 0; i < 2; i++) {
        float4 o;
        o.x = acc[i][0]; o.y = acc[i][1]; o.z = acc[i][2]; o.w = acc[i][3];
        *reinterpret_cast<float4*>(&C[(size_t)(m0 + (ty << 1) + i) * 16 + (tx << 2)]) = o;
    }
}

// ---------------------------------------------------------------------------
// Fused per-step attention kernel, one warp per batch element b:
//   y_t = (t==0) ? last_x_rel : h_t@Wo + bo        (writes ys[t-1] for t>=1)
//   compab_n = Wc2 . tanh(pre[n,b] + hproj[b])     (bc2 dropped: softmax-invariant)
//   alpha = softmax_n; wa = sum_n alpha_n * ig[n,b]
//   emb = wa + y0*We[64] + y1*We[65] + be
// ---------------------------------------------------------------------------
__global__ void attn_kernel(int t, int B,
                            const float* __restrict__ lastx,
                            const float* __restrict__ Wc2,
                            const float* __restrict__ We,
                            const float* __restrict__ be,
                            const float* __restrict__ Wo,
                            const float* __restrict__ bo,
                            float* __restrict__ out)
{
    const int lane = threadIdx.x & 31;
    const int b = blockIdx.x * 8 + (threadIdx.x >> 5);
    if (b >= B) return;

    float y0, y1;
    if (t == 0) {
        y0 = lastx[2 * b];
        y1 = lastx[2 * b + 1];
    } else {
        float h0 = g_h[(size_t)b * 64 + lane];
        float h1 = g_h[(size_t)b * 64 + 32 + lane];
        float s0 = h0 * Wo[lane * 2]     + h1 * Wo[(lane + 32) * 2];
        float s1 = h0 * Wo[lane * 2 + 1] + h1 * Wo[(lane + 32) * 2 + 1];
        #pragma unroll
        for (int m = 16; m > 0; m >>= 1) {
            s0 += __shfl_xor_sync(0xffffffffu, s0, m);
            s1 += __shfl_xor_sync(0xffffffffu, s1, m);
        }
        y0 = s0 + bo[0];
        y1 = s1 + bo[1];
        if (lane == 0) {
            out[((size_t)(t - 1) * B + b) * 2 + 0] = y0;
            out[((size_t)(t - 1) * B + b) * 2 + 1] = y1;
        }
    }

    const float hp0 = g_gemm[(size_t)b * 256 + lane];
    const float hp1 = g_gemm[(size_t)b * 256 + 32 + lane];
    const float wc2a = Wc2[lane];
    const float wc2b = Wc2[lane + 32];

    float cn[ND];
    #pragma unroll
    for (int n = 0; n < ND; n++) {
        const float* pr = g_pre + (((size_t)n * B + b) << 6);
        float c = tanhf(pr[lane] + hp0) * wc2a + tanhf(pr[lane + 32] + hp1) * wc2b;
        #pragma unroll
        for (int m = 16; m > 0; m >>= 1) c += __shfl_xor_sync(0xffffffffu, c, m);
        cn[n] = c;
    }

    float mx = cn[0];
    #pragma unroll
    for (int n = 1; n < ND; n++) mx = fmaxf(mx, cn[n]);
    float s = 0.f;
    #pragma unroll
    for (int n = 0; n < ND; n++) { cn[n] = __expf(cn[n] - mx); s += cn[n]; }
    const float inv = 1.f / s;

    if (lane < 16) {
        float wa = 0.f;
        #pragma unroll
        for (int n = 0; n < ND; n++)
            wa = fmaf(cn[n], g_ig[(((size_t)n * B + b) << 4) + lane], wa);
        wa *= inv;
        float emb = wa + y0 * We[64 * 16 + lane] + y1 * We[65 * 16 + lane] + be[lane];
        g_emb[(size_t)b * 16 + lane] = emb;
    }
}

// ---------------------------------------------------------------------------
// GRU update. gh (= h@Whh + bhh) comes from g_gemm[:,64:256].
// gi = emb@Wih + bih computed here with Wih columns hoisted to registers
// (reused across 32 batch elements -> almost no shared-memory pressure).
// ---------------------------------------------------------------------------
__global__ void gru_kernel(int B,
                           const float* __restrict__ Wih,
                           const float* __restrict__ bih)
{
    __shared__ float semb[64][16];
    const int tid = threadIdx.x;
    const int b0 = blockIdx.x * 64;

    #pragma unroll
    for (int i = 0; i < 8; i++) {
        int idx = tid + i * 128;
        semb[idx >> 4][idx & 15] = g_emb[(size_t)b0 * 16 + idx];
    }

    const int j = tid & 63;
    const int half = tid >> 6;

    float wr[16], wz[16], wn[16];
    #pragma unroll
    for (int k = 0; k < 16; k++) {
        wr[k] = Wih[k * 192 + j];
        wz[k] = Wih[k * 192 + 64 + j];
        wn[k] = Wih[k * 192 + 128 + j];
    }
    const float bir = bih[j], biz = bih[64 + j], bin = bih[128 + j];
    __syncthreads();

    for (int bb = half * 32; bb < half * 32 + 32; bb++) {
        const int b = b0 + bb;
        float gr = bir, gz = biz, gn = bin;
        #pragma unroll
        for (int k = 0; k < 16; k++) {
            float e = semb[bb][k];
            gr = fmaf(e, wr[k], gr);
            gz = fmaf(e, wz[k], gz);
            gn = fmaf(e, wn[k], gn);
        }
        const float* gg = g_gemm + (size_t)b * 256;
        float r = sigmoidf_(gr + gg[64 + j]);
        float z = sigmoidf_(gz + gg[128 + j]);
        float n = tanhf(gn + r * gg[192 + j]);
        size_t hi = (size_t)b * 64 + j;
        g_h[hi] = (1.f - z) * n + z * g_h[hi];
    }
}

// ---------------------------------------------------------------------------
// Final output row: ys[pred_len-1] = h_final @ Wo + bo
// ---------------------------------------------------------------------------
__global__ void final_y_kernel(int B, int t,
                               const float* __restrict__ Wo,
                               const float* __restrict__ bo,
                               float* __restrict__ out)
{
    const int lane = threadIdx.x & 31;
    const int b = blockIdx.x * 8 + (threadIdx.x >> 5);
    if (b >= B) return;
    float h0 = g_h[(size_t)b * 64 + lane];
    float h1 = g_h[(size_t)b * 64 + 32 + lane];
    float s0 = h0 * Wo[lane * 2]     + h1 * Wo[(lane + 32) * 2];
    float s1 = h0 * Wo[lane * 2 + 1] + h1 * Wo[(lane + 32) * 2 + 1];
    #pragma unroll
    for (int m = 16; m > 0; m >>= 1) {
        s0 += __shfl_xor_sync(0xffffffffu, s0, m);
        s1 += __shfl_xor_sync(0xffffffffu, s1, m);
    }
    if (lane == 0) {
        out[((size_t)t * B + b) * 2 + 0] = s0 + bo[0];
        out[((size_t)t * B + b) * 2 + 1] = s1 + bo[1];
    }
}

// ---------------------------------------------------------------------------
// Host launcher
// ---------------------------------------------------------------------------
extern "C" void kernel_launch(void* const* d_in, const int* in_sizes, int n_in,
                              void* d_out, int out_size)
{
    // pred_len may be passed as a size-1 leading input (setup_inputs dict order)
    // or not at all; detect via in_sizes[0].
    const int o = (in_sizes[0] == 1) ? 1 : 0;

    const float* lastx = (const float*)d_in[o + 0];
    const float* zo    = (const float*)d_in[o + 1];
    // d_in[o+2] = zg (values unused by the math)
    const float* inter = (const float*)d_in[o + 3];
    const float* We    = (const float*)d_in[o + 4];
    const float* be    = (const float*)d_in[o + 5];
    const float* Wih   = (const float*)d_in[o + 6];
    const float* Whh   = (const float*)d_in[o + 7];
    const float* bih   = (const float*)d_in[o + 8];
    const float* bhh   = (const float*)d_in[o + 9];
    const float* Wc1   = (const float*)d_in[o + 10];
    const float* bc1   = (const float*)d_in[o + 11];
    const float* Wc2   = (const float*)d_in[o + 12];
    // d_in[o+13] = bc2 (softmax-invariant; dropped)
    const float* Wo    = (const float*)d_in[o + 14];
    const float* bo    = (const float*)d_in[o + 15];
    float* out = (float*)d_out;

    const int B = in_sizes[o + 0] / 2;
    const int nd = in_sizes[o + 3] / (64 * B);   // expected == ND (20)
    const int pred_len = out_size / (2 * B);
    (void)nd; (void)n_in;

    float *pre_p, *ig_p, *gemm_p, *h_p;
    cudaGetSymbolAddress((void**)&pre_p,  g_pre);
    cudaGetSymbolAddress((void**)&ig_p,   g_ig);
    cudaGetSymbolAddress((void**)&gemm_p, g_gemm);
    cudaGetSymbolAddress((void**)&h_p,    g_h);

    // h <- zo[-1]
    copy_h_kernel<<<(B * 64 + 255) / 256, 256>>>(zo, B * 64);

    // Precompute (time-invariant):
    //   pre = intermediate @ Wc1[:64] + bc1
    //   ig  = intermediate @ We[:64]
    const int Mrows = ND * B;
    gemm64_kernel<<<dim3(Mrows / 64, 1), 128>>>(inter, Wc1, 64, bc1, pre_p, 64);
    gemm16_kernel<<<dim3(Mrows / 64, 1), 128>>>(inter, We, ig_p);

    for (int t = 0; t < pred_len; t++) {
        // hproj = h @ Wc1[64:]          -> g_gemm[:, 0:64]
        gemm64_kernel<<<dim3(B / 64, 1), 128>>>(h_p, Wc1 + 64 * 64, 64, nullptr,
                                                gemm_p, 256);
        // gh = h @ Whh + bhh            -> g_gemm[:, 64:256]
        gemm64_kernel<<<dim3(B / 64, 3), 128>>>(h_p, Whh, 192, bhh,
                                                gemm_p + 64, 256);
        // attention + softmax + embedding (+ y_t / ys[t-1])
        attn_kernel<<<B / 8, 256>>>(t, B, lastx, Wc2, We, be, Wo, bo, out);
        // GRU state update
        gru_kernel<<<B / 64, 128>>>(B, Wih, bih);
    }

    // ys[pred_len-1] = h_final @ Wo + bo
    final_y_kernel<<<B / 8, 256>>>(B, pred_len - 1, Wo, bo, out);
}

// round 3
// speedup vs baseline: 1.4143x; 1.4143x over previous
#include <cuda_runtime.h>
#include <cuda_fp16.h>
#include <cstdint>
#include <cstddef>

// Problem constants (fixed by the dataset): B=16384, ND=20, D_G=D_H=64, D_EMB=16.
#define MAXB 16384
#define ND 20

// Scratch (static device globals; no allocation at runtime).
__device__ __half g_preh[(size_t)ND * MAXB * 64];  // intermediate @ Wc1[:64] + bc1   (42 MB, fp16)
__device__ __half g_igh [(size_t)ND * MAXB * 16];  // intermediate @ We[:64]          (10.5 MB, fp16)
__device__ float  g_gemm[(size_t)MAXB * 256];      // per-step: [0:64)=hproj, [64:256)=gh
__device__ float  g_h   [(size_t)MAXB * 64];       // recurrent hidden state
__device__ float  g_emb [(size_t)MAXB * 16];       // per-step GRU input embedding
__device__ float  g_W256[64 * 256];                // combined [Wc1[64:,:] | Whh]
__device__ float  g_b256[256];                     // [0]*64 | bhh

__device__ __forceinline__ float sigmoidf_(float x) { return 1.f / (1.f + __expf(-x)); }
__device__ __forceinline__ float tanh_hw(float x) {
    float y; asm("tanh.approx.f32 %0, %1;" : "=f"(y) : "f"(x)); return y;
}

// ---------------------------------------------------------------------------
// init: h <- zo[-1] (zo is (1,B,64))
// ---------------------------------------------------------------------------
__global__ void copy_h_kernel(const float* __restrict__ zo, int n)
{
    int i = blockIdx.x * blockDim.x + threadIdx.x;
    if (i < n) g_h[i] = zo[i];
}

// Build combined per-step weight/bias (once per launch; deterministic).
__global__ void prep_kernel(const float* __restrict__ Wc1,
                            const float* __restrict__ Whh,
                            const float* __restrict__ bhh)
{
    int i = blockIdx.x * blockDim.x + threadIdx.x;
    if (i < 64 * 256) {
        int k = i >> 8, n = i & 255;
        g_W256[i] = (n < 64) ? Wc1[(64 + k) * 64 + n] : Whh[k * 192 + (n - 64)];
    }
    if (i < 256) g_b256[i] = (i < 64) ? 0.f : bhh[i - 64];
}

// ---------------------------------------------------------------------------
// C[m0:m0+64, n0:n0+64] = A[m0:m0+64, 0:64] @ W[0:64, n0:n0+64] (+ bias)
// A row-major lda=64. W row-major with ldW. 128 threads, 8x4 microtile.
// Templated on output type (float for per-step, __half for precompute).
// ---------------------------------------------------------------------------
template <typename OT>
__global__ void gemm64_kernel(const float* __restrict__ A,
                              const float* __restrict__ W, int ldW,
                              const float* __restrict__ bias,
                              OT* __restrict__ C, int ldC)
{
    __shared__ float As[64][68];   // k-major, padded
    __shared__ float Ws[64][64];

    const int tid = threadIdx.x;
    const int m0  = blockIdx.x * 64;
    const int n0  = blockIdx.y * 64;

    const float4* Ag = reinterpret_cast<const float4*>(A + (size_t)m0 * 64);
    #pragma unroll
    for (int i = 0; i < 8; i++) {
        int idx = tid + i * 128;
        int r = idx >> 4, k4 = (idx & 15) << 2;
        float4 v = Ag[idx];
        As[k4 + 0][r] = v.x; As[k4 + 1][r] = v.y;
        As[k4 + 2][r] = v.z; As[k4 + 3][r] = v.w;
    }
    #pragma unroll
    for (int i = 0; i < 32; i++) {
        int idx = tid + i * 128;
        int k = idx >> 6, n = idx & 63;
        Ws[k][n] = W[(size_t)k * ldW + n0 + n];
    }
    __syncthreads();

    const int tx = tid & 15;
    const int ty = tid >> 4;

    float acc[8][4];
    #pragma unroll
    for (int i = 0; i < 8; i++)
        #pragma unroll
        for (int j = 0; j < 4; j++) acc[i][j] = 0.f;

    #pragma unroll
    for (int k = 0; k < 64; k++) {
        float4 w  = *reinterpret_cast<const float4*>(&Ws[k][tx << 2]);
        float4 a0 = *reinterpret_cast<const float4*>(&As[k][ty << 3]);
        float4 a1 = *reinterpret_cast<const float4*>(&As[k][(ty << 3) + 4]);
        float av[8] = {a0.x, a0.y, a0.z, a0.w, a1.x, a1.y, a1.z, a1.w};
        float wv[4] = {w.x, w.y, w.z, w.w};
        #pragma unroll
        for (int i = 0; i < 8; i++)
            #pragma unroll
            for (int j = 0; j < 4; j++)
                acc[i][j] = fmaf(av[i], wv[j], acc[i][j]);
    }

    float bv[4] = {0.f, 0.f, 0.f, 0.f};
    if (bias) {
        #pragma unroll
        for (int j = 0; j < 4; j++) bv[j] = bias[n0 + (tx << 2) + j];
    }
    #pragma unroll
    for (int i = 0; i < 8; i++) {
        #pragma unroll
        for (int j = 0; j < 4; j++)
            C[(size_t)(m0 + (ty << 3) + i) * ldC + n0 + (tx << 2) + j] =
                (OT)(acc[i][j] + bv[j]);
    }
}

// ---------------------------------------------------------------------------
// ig = A[M,64] @ W[64,16]  (W = first 64 rows of We), fp16 out, ldC = 16
// ---------------------------------------------------------------------------
__global__ void gemm16_kernel(const float* __restrict__ A,
                              const float* __restrict__ W,
                              __half* __restrict__ C)
{
    __shared__ float As[64][68];
    __shared__ float Ws[64][16];

    const int tid = threadIdx.x;
    const int m0  = blockIdx.x * 64;

    const float4* Ag = reinterpret_cast<const float4*>(A + (size_t)m0 * 64);
    #pragma unroll
    for (int i = 0; i < 8; i++) {
        int idx = tid + i * 128;
        int r = idx >> 4, k4 = (idx & 15) << 2;
        float4 v = Ag[idx];
        As[k4 + 0][r] = v.x; As[k4 + 1][r] = v.y;
        As[k4 + 2][r] = v.z; As[k4 + 3][r] = v.w;
    }
    #pragma unroll
    for (int i = 0; i < 8; i++) {
        int idx = tid + i * 128;
        int k = idx >> 4, n = idx & 15;
        Ws[k][n] = W[k * 16 + n];
    }
    __syncthreads();

    const int tx = tid & 3;
    const int ty = tid >> 2;

    float acc[2][4];
    #pragma unroll
    for (int i = 0; i < 2; i++)
        #pragma unroll
        for (int j = 0; j < 4; j++) acc[i][j] = 0.f;

    #pragma unroll
    for (int k = 0; k < 64; k++) {
        float4 w  = *reinterpret_cast<const float4*>(&Ws[k][tx << 2]);
        float a0 = As[k][(ty << 1) + 0];
        float a1 = As[k][(ty << 1) + 1];
        acc[0][0] = fmaf(a0, w.x, acc[0][0]); acc[0][1] = fmaf(a0, w.y, acc[0][1]);
        acc[0][2] = fmaf(a0, w.z, acc[0][2]); acc[0][3] = fmaf(a0, w.w, acc[0][3]);
        acc[1][0] = fmaf(a1, w.x, acc[1][0]); acc[1][1] = fmaf(a1, w.y, acc[1][1]);
        acc[1][2] = fmaf(a1, w.z, acc[1][2]); acc[1][3] = fmaf(a1, w.w, acc[1][3]);
    }
    #pragma unroll
    for (int i = 0; i < 2; i++) {
        __half2 h01 = __floats2half2_rn(acc[i][0], acc[i][1]);
        __half2 h23 = __floats2half2_rn(acc[i][2], acc[i][3]);
        __half2* cp = reinterpret_cast<__half2*>(
            &C[(size_t)(m0 + (ty << 1) + i) * 16 + (tx << 2)]);
        cp[0] = h01; cp[1] = h23;
    }
}

// ---------------------------------------------------------------------------
// Fused per-step attention kernel, one warp per batch element b.
// pre/ig are fp16; tanh is the HW approx instruction.
// ---------------------------------------------------------------------------
__global__ void attn_kernel(int t, int B,
                            const float* __restrict__ lastx,
                            const float* __restrict__ Wc2,
                            const float* __restrict__ We,
                            const float* __restrict__ be,
                            const float* __restrict__ Wo,
                            const float* __restrict__ bo,
                            float* __restrict__ out)
{
    const int lane = threadIdx.x & 31;
    const int b = blockIdx.x * 8 + (threadIdx.x >> 5);
    if (b >= B) return;

    float y0, y1;
    if (t == 0) {
        y0 = lastx[2 * b];
        y1 = lastx[2 * b + 1];
    } else {
        float h0 = g_h[(size_t)b * 64 + lane];
        float h1 = g_h[(size_t)b * 64 + 32 + lane];
        float s0 = h0 * Wo[lane * 2]     + h1 * Wo[(lane + 32) * 2];
        float s1 = h0 * Wo[lane * 2 + 1] + h1 * Wo[(lane + 32) * 2 + 1];
        #pragma unroll
        for (int m = 16; m > 0; m >>= 1) {
            s0 += __shfl_xor_sync(0xffffffffu, s0, m);
            s1 += __shfl_xor_sync(0xffffffffu, s1, m);
        }
        y0 = s0 + bo[0];
        y1 = s1 + bo[1];
        if (lane == 0) {
            out[((size_t)(t - 1) * B + b) * 2 + 0] = y0;
            out[((size_t)(t - 1) * B + b) * 2 + 1] = y1;
        }
    }

    // lane owns k = 2*lane and 2*lane+1
    const float hpA  = g_gemm[(size_t)b * 256 + 2 * lane];
    const float hpB  = g_gemm[(size_t)b * 256 + 2 * lane + 1];
    const float wc2A = Wc2[2 * lane];
    const float wc2B = Wc2[2 * lane + 1];

    const __half2* preh2 = reinterpret_cast<const __half2*>(g_preh);

    float cn[ND];
    #pragma unroll
    for (int n = 0; n < ND; n++) {
        float2 p = __half22float2(preh2[(((size_t)n * B + b) << 5) + lane]);
        float c = tanh_hw(p.x + hpA) * wc2A + tanh_hw(p.y + hpB) * wc2B;
        #pragma unroll
        for (int m = 16; m > 0; m >>= 1) c += __shfl_xor_sync(0xffffffffu, c, m);
        cn[n] = c;
    }

    float mx = cn[0];
    #pragma unroll
    for (int n = 1; n < ND; n++) mx = fmaxf(mx, cn[n]);
    float s = 0.f;
    #pragma unroll
    for (int n = 0; n < ND; n++) { cn[n] = __expf(cn[n] - mx); s += cn[n]; }
    const float inv = 1.f / s;

    if (lane < 16) {
        float wa = 0.f;
        #pragma unroll
        for (int n = 0; n < ND; n++)
            wa = fmaf(cn[n], __half2float(g_igh[(((size_t)n * B + b) << 4) + lane]), wa);
        wa *= inv;
        float emb = wa + y0 * We[64 * 16 + lane] + y1 * We[65 * 16 + lane] + be[lane];
        g_emb[(size_t)b * 16 + lane] = emb;
    }
}

// ---------------------------------------------------------------------------
// GRU update. gh (= h@Whh + bhh) comes from g_gemm[:,64:256].
// ---------------------------------------------------------------------------
__global__ void gru_kernel(int B,
                           const float* __restrict__ Wih,
                           const float* __restrict__ bih)
{
    __shared__ float semb[64][16];
    const int tid = threadIdx.x;
    const int b0 = blockIdx.x * 64;

    #pragma unroll
    for (int i = 0; i < 8; i++) {
        int idx = tid + i * 128;
        semb[idx >> 4][idx & 15] = g_emb[(size_t)b0 * 16 + idx];
    }

    const int j = tid & 63;
    const int half = tid >> 6;

    float wr[16], wz[16], wn[16];
    #pragma unroll
    for (int k = 0; k < 16; k++) {
        wr[k] = Wih[k * 192 + j];
        wz[k] = Wih[k * 192 + 64 + j];
        wn[k] = Wih[k * 192 + 128 + j];
    }
    const float bir = bih[j], biz = bih[64 + j], bin = bih[128 + j];
    __syncthreads();

    for (int bb = half * 32; bb < half * 32 + 32; bb++) {
        const int b = b0 + bb;
        float gr = bir, gz = biz, gn = bin;
        #pragma unroll
        for (int k = 0; k < 16; k++) {
            float e = semb[bb][k];
            gr = fmaf(e, wr[k], gr);
            gz = fmaf(e, wz[k], gz);
            gn = fmaf(e, wn[k], gn);
        }
        const float* gg = g_gemm + (size_t)b * 256;
        float r = sigmoidf_(gr + gg[64 + j]);
        float z = sigmoidf_(gz + gg[128 + j]);
        float n = tanhf(gn + r * gg[192 + j]);
        size_t hi = (size_t)b * 64 + j;
        g_h[hi] = (1.f - z) * n + z * g_h[hi];
    }
}

// ---------------------------------------------------------------------------
// Final output row: ys[pred_len-1] = h_final @ Wo + bo
// ---------------------------------------------------------------------------
__global__ void final_y_kernel(int B, int t,
                               const float* __restrict__ Wo,
                               const float* __restrict__ bo,
                               float* __restrict__ out)
{
    const int lane = threadIdx.x & 31;
    const int b = blockIdx.x * 8 + (threadIdx.x >> 5);
    if (b >= B) return;
    float h0 = g_h[(size_t)b * 64 + lane];
    float h1 = g_h[(size_t)b * 64 + 32 + lane];
    float s0 = h0 * Wo[lane * 2]     + h1 * Wo[(lane + 32) * 2];
    float s1 = h0 * Wo[lane * 2 + 1] + h1 * Wo[(lane + 32) * 2 + 1];
    #pragma unroll
    for (int m = 16; m > 0; m >>= 1) {
        s0 += __shfl_xor_sync(0xffffffffu, s0, m);
        s1 += __shfl_xor_sync(0xffffffffu, s1, m);
    }
    if (lane == 0) {
        out[((size_t)t * B + b) * 2 + 0] = s0 + bo[0];
        out[((size_t)t * B + b) * 2 + 1] = s1 + bo[1];
    }
}

// ---------------------------------------------------------------------------
// Host launcher
// ---------------------------------------------------------------------------
extern "C" void kernel_launch(void* const* d_in, const int* in_sizes, int n_in,
                              void* d_out, int out_size)
{
    const int o = (in_sizes[0] == 1) ? 1 : 0;

    const float* lastx = (const float*)d_in[o + 0];
    const float* zo    = (const float*)d_in[o + 1];
    const float* inter = (const float*)d_in[o + 3];
    const float* We    = (const float*)d_in[o + 4];
    const float* be    = (const float*)d_in[o + 5];
    const float* Wih   = (const float*)d_in[o + 6];
    const float* Whh   = (const float*)d_in[o + 7];
    const float* bih   = (const float*)d_in[o + 8];
    const float* bhh   = (const float*)d_in[o + 9];
    const float* Wc1   = (const float*)d_in[o + 10];
    const float* bc1   = (const float*)d_in[o + 11];
    const float* Wc2   = (const float*)d_in[o + 12];
    const float* Wo    = (const float*)d_in[o + 14];
    const float* bo    = (const float*)d_in[o + 15];
    float* out = (float*)d_out;

    const int B = in_sizes[o + 0] / 2;
    const int pred_len = out_size / (2 * B);
    (void)n_in;

    __half *preh_p, *igh_p;
    float *gemm_p, *h_p, *W256_p, *b256_p;
    cudaGetSymbolAddress((void**)&preh_p, g_preh);
    cudaGetSymbolAddress((void**)&igh_p,  g_igh);
    cudaGetSymbolAddress((void**)&gemm_p, g_gemm);
    cudaGetSymbolAddress((void**)&h_p,    g_h);
    cudaGetSymbolAddress((void**)&W256_p, g_W256);
    cudaGetSymbolAddress((void**)&b256_p, g_b256);

    copy_h_kernel<<<(B * 64 + 255) / 256, 256>>>(zo, B * 64);
    prep_kernel<<<64, 256>>>(Wc1, Whh, bhh);

    // Precompute (time-invariant): pre (fp16) and ig (fp16)
    const int Mrows = ND * B;
    gemm64_kernel<__half><<<dim3(Mrows / 64, 1), 128>>>(inter, Wc1, 64, bc1,
                                                        preh_p, 64);
    gemm16_kernel<<<dim3(Mrows / 64, 1), 128>>>(inter, We, igh_p);

    for (int t = 0; t < pred_len; t++) {
        // [hproj | gh] = h @ W256 + b256  -> g_gemm[:,0:256]   (one launch, grid 1024)
        gemm64_kernel<float><<<dim3(B / 64, 4), 128>>>(h_p, W256_p, 256, b256_p,
                                                       gemm_p, 256);
        attn_kernel<<<B / 8, 256>>>(t, B, lastx, Wc2, We, be, Wo, bo, out);
        gru_kernel<<<B / 64, 128>>>(B, Wih, bih);
    }

    final_y_kernel<<<B / 8, 256>>>(B, pred_len - 1, Wo, bo, out);
}

// round 4
// speedup vs baseline: 2.0829x; 1.4728x over previous
#include <cuda_runtime.h>
#include <cuda_fp16.h>
#include <cstdint>
#include <cstddef>

// Problem constants: B=16384, ND=20, D_G=D_H=64, D_EMB=16, pred_len=12.
#define MAXB 16384
#define ND 20
#define BPB 64          // batch elements per block in the fused step kernel

typedef unsigned long long ull;

// Time-invariant precompute scratch (fp16).
__device__ __half g_preh[(size_t)ND * MAXB * 64];  // intermediate @ Wc1[:64] + bc1
__device__ __half g_igh [(size_t)ND * MAXB * 16];  // intermediate @ We[:64]

__device__ __forceinline__ float sigmoidf_(float x) { return 1.f / (1.f + __expf(-x)); }
__device__ __forceinline__ float tanh_hw(float x) {
    float y; asm("tanh.approx.f32 %0, %1;" : "=f"(y) : "f"(x)); return y;
}

// ---------------------------------------------------------------------------
// Precompute (one pass over intermediate):
//   pre[m][0:64] = A[m] @ Wc1[:64]  + bc1   (fp16)
//   ig [m][0:16] = A[m] @ We[:64]           (fp16)
// Tile: 64 rows x 80 cols, 128 threads, 8x5 microtile.
// ---------------------------------------------------------------------------
__global__ void precomp_kernel(const float* __restrict__ A,
                               const float* __restrict__ Wc1,
                               const float* __restrict__ bc1,
                               const float* __restrict__ We)
{
    __shared__ float As[64][68];   // k-major, padded
    __shared__ float Ws[64][80];

    const int tid = threadIdx.x;
    const int m0  = blockIdx.x * 64;

    const float4* Ag = reinterpret_cast<const float4*>(A + (size_t)m0 * 64);
    #pragma unroll
    for (int i = 0; i < 8; i++) {
        int idx = tid + i * 128;
        int r = idx >> 4, k4 = (idx & 15) << 2;
        float4 v = Ag[idx];
        As[k4 + 0][r] = v.x; As[k4 + 1][r] = v.y;
        As[k4 + 2][r] = v.z; As[k4 + 3][r] = v.w;
    }
    for (int i = tid; i < 64 * 80; i += 128) {
        int k = i / 80, c = i - k * 80;
        Ws[k][c] = (c < 64) ? Wc1[k * 64 + c] : We[k * 16 + (c - 64)];
    }
    __syncthreads();

    const int tx = tid & 15;    // col group: cols tx + 16*jj
    const int ty = tid >> 4;    // row group: rows ty*8 .. +7

    float acc[8][5];
    #pragma unroll
    for (int i = 0; i < 8; i++)
        #pragma unroll
        for (int j = 0; j < 5; j++) acc[i][j] = 0.f;

    #pragma unroll 4
    for (int k = 0; k < 64; k++) {
        float wv[5];
        #pragma unroll
        for (int j = 0; j < 5; j++) wv[j] = Ws[k][tx + 16 * j];
        float4 a0 = *reinterpret_cast<const float4*>(&As[k][ty << 3]);
        float4 a1 = *reinterpret_cast<const float4*>(&As[k][(ty << 3) + 4]);
        float av[8] = {a0.x, a0.y, a0.z, a0.w, a1.x, a1.y, a1.z, a1.w};
        #pragma unroll
        for (int i = 0; i < 8; i++)
            #pragma unroll
            for (int j = 0; j < 5; j++)
                acc[i][j] = fmaf(av[i], wv[j], acc[i][j]);
    }

    #pragma unroll
    for (int j = 0; j < 5; j++) {
        int c = tx + 16 * j;
        float bv = (c < 64) ? bc1[c] : 0.f;
        #pragma unroll
        for (int i = 0; i < 8; i++) {
            int r = m0 + (ty << 3) + i;
            float v = acc[i][j] + bv;
            if (c < 64) g_preh[(size_t)r * 64 + c]        = __float2half_rn(v);
            else        g_igh [(size_t)r * 16 + (c - 64)] = __float2half_rn(v);
        }
    }
}

// ---------------------------------------------------------------------------
// Fused persistent step kernel: one block owns BPB=64 batch elements for all
// pred_len steps. h lives in smem; weights live in smem. Per step:
//   Phase A: G[64][256] = h @ [Wc1h | Whh] (+[0|bhh])   (f32x2 packed FMA)
//   Phase B: warp-per-b attention (fp16 pre/ig stream, tanh.approx),
//            y output, emb -> smem
//   Phase C: GRU gate math, h updated in smem
// ---------------------------------------------------------------------------
// Dynamic smem layout (float offsets):
#define SW_OFF    0            // [64][256] combined W          16384
#define SG_OFF    16384        // [64][256] gemm out            16384
#define SH_OFF    32768        // [64][68]  h (padded)           4352
#define SWIH_OFF  37120        // [16][192] Wih                  3072
#define SEMB_OFF  40192        // [64][16]  emb                  1024
#define SB_OFF    41216        // [256]     [0|bhh]               256
#define SBIH_OFF  41472        // [192]     bih                   192
#define SWO_OFF   41664        // [128]     Wo                    128
#define SWC2_OFF  41792        // [64]      Wc2                    64
#define SWEY_OFF  41856        // [32]      We rows 64,65          32
#define SBE_OFF   41888        // [16]      be                     16
#define SBO_OFF   41904        // [2]       bo                      2
#define SMEM_FLOATS 41908
#define SMEM_BYTES  (SMEM_FLOATS * 4)

__global__ void __launch_bounds__(256, 1)
step_kernel(const float* __restrict__ lastx,
            const float* __restrict__ zo,
            const float* __restrict__ Wc1,
            const float* __restrict__ Whh,
            const float* __restrict__ bhh,
            const float* __restrict__ Wih,
            const float* __restrict__ bih,
            const float* __restrict__ Wc2,
            const float* __restrict__ We,
            const float* __restrict__ be,
            const float* __restrict__ Wo,
            const float* __restrict__ bo,
            float* __restrict__ out,
            int B, int pred_len)
{
    extern __shared__ float sm[];
    float* sW   = sm + SW_OFF;
    float* sG   = sm + SG_OFF;
    float* sh   = sm + SH_OFF;
    float* sWih = sm + SWIH_OFF;
    float* semb = sm + SEMB_OFF;
    float* sb   = sm + SB_OFF;
    float* sbih = sm + SBIH_OFF;
    float* sWo  = sm + SWO_OFF;
    float* sWc2 = sm + SWC2_OFF;
    float* sWeY = sm + SWEY_OFF;
    float* sbe  = sm + SBE_OFF;
    float* sbo  = sm + SBO_OFF;

    const int tid  = threadIdx.x;
    const int lane = tid & 31;
    const int wrp  = tid >> 5;
    const int b0   = blockIdx.x * BPB;

    // ---- init: weights + h ----
    for (int i = tid; i < 64 * 256; i += 256) {
        int k = i >> 8, c = i & 255;
        sW[i] = (c < 64) ? Wc1[(64 + k) * 64 + c] : Whh[k * 192 + (c - 64)];
    }
    for (int i = tid; i < 16 * 192; i += 256) sWih[i] = Wih[i];
    sb[tid] = (tid < 64) ? 0.f : bhh[tid - 64];
    if (tid < 192) sbih[tid] = bih[tid];
    if (tid < 128) sWo[tid]  = Wo[tid];
    if (tid < 64)  sWc2[tid] = Wc2[tid];
    if (tid < 32)  sWeY[tid] = We[64 * 16 + tid];
    if (tid < 16)  sbe[tid]  = be[tid];
    if (tid < 2)   sbo[tid]  = bo[tid];
    for (int i = tid; i < BPB * 64; i += 256) {
        int r = i >> 6, k = i & 63;
        sh[r * 68 + k] = zo[(size_t)(b0 + r) * 64 + k];
    }
    __syncthreads();

    const __half2* preh2 = reinterpret_cast<const __half2*>(g_preh);

    for (int t = 0; t < pred_len; t++) {
        // ================= Phase A: G = h @ W (+b) =================
        {
            ull acc2[8][4];
            #pragma unroll
            for (int i = 0; i < 8; i++)
                #pragma unroll
                for (int j = 0; j < 4; j++) acc2[i][j] = 0ull;

            #pragma unroll 4
            for (int k = 0; k < 64; k++) {
                ull wv[4];
                #pragma unroll
                for (int j = 0; j < 4; j++)
                    wv[j] = *reinterpret_cast<const ull*>(
                        &sW[k * 256 + 2 * lane + 64 * j]);
                #pragma unroll
                for (int i = 0; i < 8; i++) {
                    float hv = sh[(wrp * 8 + i) * 68 + k];
                    ull h2;
                    asm("mov.b64 %0, {%1, %1};" : "=l"(h2) : "f"(hv));
                    #pragma unroll
                    for (int j = 0; j < 4; j++)
                        asm("fma.rn.f32x2 %0, %1, %2, %0;"
                            : "+l"(acc2[i][j]) : "l"(h2), "l"(wv[j]));
                }
            }
            #pragma unroll
            for (int i = 0; i < 8; i++) {
                int r = wrp * 8 + i;
                #pragma unroll
                for (int j = 0; j < 4; j++) {
                    int c = 2 * lane + 64 * j;
                    float2 v = *reinterpret_cast<float2*>(&acc2[i][j]);
                    float2 o; o.x = v.x + sb[c]; o.y = v.y + sb[c + 1];
                    *reinterpret_cast<float2*>(&sG[r * 256 + c]) = o;
                }
            }
        }
        __syncthreads();

        // ================= Phase B: attention (warp-per-b, 8 b per warp) =====
        {
            const float wA = sWc2[2 * lane];
            const float wB = sWc2[2 * lane + 1];
            #pragma unroll 1
            for (int i = 0; i < 8; i++) {
                const int bl = wrp * 8 + i;
                const int bg = b0 + bl;

                float y0, y1;
                if (t == 0) {
                    y0 = lastx[2 * bg];
                    y1 = lastx[2 * bg + 1];
                } else {
                    float h0 = sh[bl * 68 + lane];
                    float h1 = sh[bl * 68 + 32 + lane];
                    float s0 = h0 * sWo[lane * 2]     + h1 * sWo[(lane + 32) * 2];
                    float s1 = h0 * sWo[lane * 2 + 1] + h1 * sWo[(lane + 32) * 2 + 1];
                    #pragma unroll
                    for (int m = 16; m > 0; m >>= 1) {
                        s0 += __shfl_xor_sync(0xffffffffu, s0, m);
                        s1 += __shfl_xor_sync(0xffffffffu, s1, m);
                    }
                    y0 = s0 + sbo[0];
                    y1 = s1 + sbo[1];
                    if (lane == 0) {
                        out[((size_t)(t - 1) * B + bg) * 2 + 0] = y0;
                        out[((size_t)(t - 1) * B + bg) * 2 + 1] = y1;
                    }
                }

                const float hpA = sG[bl * 256 + 2 * lane];
                const float hpB = sG[bl * 256 + 2 * lane + 1];

                float cn[ND];
                #pragma unroll
                for (int n = 0; n < ND; n++) {
                    float2 p = __half22float2(
                        preh2[(((size_t)n * B + bg) << 5) + lane]);
                    float c = tanh_hw(p.x + hpA) * wA + tanh_hw(p.y + hpB) * wB;
                    #pragma unroll
                    for (int m = 16; m > 0; m >>= 1)
                        c += __shfl_xor_sync(0xffffffffu, c, m);
                    cn[n] = c;
                }

                float mx = cn[0];
                #pragma unroll
                for (int n = 1; n < ND; n++) mx = fmaxf(mx, cn[n]);
                float s = 0.f;
                #pragma unroll
                for (int n = 0; n < ND; n++) { cn[n] = __expf(cn[n] - mx); s += cn[n]; }
                const float inv = 1.f / s;

                if (lane < 16) {
                    float wa = 0.f;
                    #pragma unroll
                    for (int n = 0; n < ND; n++)
                        wa = fmaf(cn[n],
                                  __half2float(g_igh[(((size_t)n * B + bg) << 4) + lane]),
                                  wa);
                    wa *= inv;
                    semb[bl * 16 + lane] =
                        wa + y0 * sWeY[lane] + y1 * sWeY[16 + lane] + sbe[lane];
                }
            }
        }
        __syncthreads();

        // ================= Phase C: GRU update =================
        {
            const int j    = tid & 63;
            const int bgrp = tid >> 6;      // 0..3, 16 b each
            float wr[16], wz[16], wn[16];
            #pragma unroll
            for (int k = 0; k < 16; k++) {
                wr[k] = sWih[k * 192 + j];
                wz[k] = sWih[k * 192 + 64 + j];
                wn[k] = sWih[k * 192 + 128 + j];
            }
            const float bir = sbih[j], biz = sbih[64 + j], bin = sbih[128 + j];

            for (int b = bgrp * 16; b < bgrp * 16 + 16; b++) {
                float gr = bir, gz = biz, gn = bin;
                #pragma unroll
                for (int k = 0; k < 16; k++) {
                    float e = semb[b * 16 + k];
                    gr = fmaf(e, wr[k], gr);
                    gz = fmaf(e, wz[k], gz);
                    gn = fmaf(e, wn[k], gn);
                }
                const float* gg = &sG[b * 256];
                float r = sigmoidf_(gr + gg[64 + j]);
                float z = sigmoidf_(gz + gg[128 + j]);
                float n = tanhf(gn + r * gg[192 + j]);
                sh[b * 68 + j] = (1.f - z) * n + z * sh[b * 68 + j];
            }
        }
        __syncthreads();
    }

    // ---- final output row: ys[pred_len-1] = h @ Wo + bo ----
    #pragma unroll 1
    for (int i = 0; i < 8; i++) {
        const int bl = wrp * 8 + i;
        const int bg = b0 + bl;
        float h0 = sh[bl * 68 + lane];
        float h1 = sh[bl * 68 + 32 + lane];
        float s0 = h0 * sWo[lane * 2]     + h1 * sWo[(lane + 32) * 2];
        float s1 = h0 * sWo[lane * 2 + 1] + h1 * sWo[(lane + 32) * 2 + 1];
        #pragma unroll
        for (int m = 16; m > 0; m >>= 1) {
            s0 += __shfl_xor_sync(0xffffffffu, s0, m);
            s1 += __shfl_xor_sync(0xffffffffu, s1, m);
        }
        if (lane == 0) {
            out[((size_t)(pred_len - 1) * B + bg) * 2 + 0] = s0 + sbo[0];
            out[((size_t)(pred_len - 1) * B + bg) * 2 + 1] = s1 + sbo[1];
        }
    }
}

// ---------------------------------------------------------------------------
// Host launcher: 2 kernels total.
// ---------------------------------------------------------------------------
extern "C" void kernel_launch(void* const* d_in, const int* in_sizes, int n_in,
                              void* d_out, int out_size)
{
    const int o = (in_sizes[0] == 1) ? 1 : 0;

    const float* lastx = (const float*)d_in[o + 0];
    const float* zo    = (const float*)d_in[o + 1];
    const float* inter = (const float*)d_in[o + 3];
    const float* We    = (const float*)d_in[o + 4];
    const float* be    = (const float*)d_in[o + 5];
    const float* Wih   = (const float*)d_in[o + 6];
    const float* Whh   = (const float*)d_in[o + 7];
    const float* bih   = (const float*)d_in[o + 8];
    const float* bhh   = (const float*)d_in[o + 9];
    const float* Wc1   = (const float*)d_in[o + 10];
    const float* bc1   = (const float*)d_in[o + 11];
    const float* Wc2   = (const float*)d_in[o + 12];
    const float* Wo    = (const float*)d_in[o + 14];
    const float* bo    = (const float*)d_in[o + 15];
    float* out = (float*)d_out;

    const int B = in_sizes[o + 0] / 2;
    const int pred_len = out_size / (2 * B);
    (void)n_in;

    static bool attr_done = false;
    if (!attr_done) {
        cudaFuncSetAttribute(step_kernel,
                             cudaFuncAttributeMaxDynamicSharedMemorySize,
                             SMEM_BYTES);
        attr_done = true;
    }

    // Precompute pre (fp16) + ig (fp16) in one pass over intermediate.
    precomp_kernel<<<(ND * B) / 64, 128>>>(inter, Wc1, bc1, We);

    // One persistent kernel for the whole recurrence.
    step_kernel<<<B / BPB, 256, SMEM_BYTES>>>(lastx, zo, Wc1, Whh, bhh,
                                              Wih, bih, Wc2, We, be, Wo, bo,
                                              out, B, pred_len);
}

// round 5
// speedup vs baseline: 2.5495x; 1.2240x over previous
#include <cuda_runtime.h>
#include <cuda_fp16.h>
#include <cstdint>
#include <cstddef>

// Problem constants: B=16384, ND=20, D_G=D_H=64, D_EMB=16, pred_len=12.
#define MAXB 16384
#define ND 20
#define BPB 32          // batch elements per block (4 per warp, 8 warps)

typedef unsigned long long ull;

// Time-invariant precompute scratch (fp16). 50 MB total -> L2-resident.
__device__ __half g_preh[(size_t)ND * MAXB * 64];  // intermediate @ Wc1[:64] + bc1
__device__ __half g_igh [(size_t)ND * MAXB * 16];  // intermediate @ We[:64]

__device__ __forceinline__ float sigmoidf_(float x) { return 1.f / (1.f + __expf(-x)); }
__device__ __forceinline__ float tanh_hw(float x) {
    float y; asm("tanh.approx.f32 %0, %1;" : "=f"(y) : "f"(x)); return y;
}
__device__ __forceinline__ ull pack2(float v) {
    ull r; asm("mov.b64 %0, {%1, %1};" : "=l"(r) : "f"(v)); return r;
}
__device__ __forceinline__ float2 unpack2(ull u) {
    float2 v; asm("mov.b64 {%0, %1}, %2;" : "=f"(v.x), "=f"(v.y) : "l"(u)); return v;
}

// ---------------------------------------------------------------------------
// Precompute (one pass over intermediate):
//   pre[m][0:64] = A[m] @ Wc1[:64]  + bc1   (fp16)
//   ig [m][0:16] = A[m] @ We[:64]           (fp16)
// ---------------------------------------------------------------------------
__global__ void precomp_kernel(const float* __restrict__ A,
                               const float* __restrict__ Wc1,
                               const float* __restrict__ bc1,
                               const float* __restrict__ We)
{
    __shared__ float As[64][68];   // k-major, padded
    __shared__ float Ws[64][80];

    const int tid = threadIdx.x;
    const int m0  = blockIdx.x * 64;

    const float4* Ag = reinterpret_cast<const float4*>(A + (size_t)m0 * 64);
    #pragma unroll
    for (int i = 0; i < 8; i++) {
        int idx = tid + i * 128;
        int r = idx >> 4, k4 = (idx & 15) << 2;
        float4 v = Ag[idx];
        As[k4 + 0][r] = v.x; As[k4 + 1][r] = v.y;
        As[k4 + 2][r] = v.z; As[k4 + 3][r] = v.w;
    }
    for (int i = tid; i < 64 * 80; i += 128) {
        int k = i / 80, c = i - k * 80;
        Ws[k][c] = (c < 64) ? Wc1[k * 64 + c] : We[k * 16 + (c - 64)];
    }
    __syncthreads();

    const int tx = tid & 15;
    const int ty = tid >> 4;

    float acc[8][5];
    #pragma unroll
    for (int i = 0; i < 8; i++)
        #pragma unroll
        for (int j = 0; j < 5; j++) acc[i][j] = 0.f;

    #pragma unroll 4
    for (int k = 0; k < 64; k++) {
        float wv[5];
        #pragma unroll
        for (int j = 0; j < 5; j++) wv[j] = Ws[k][tx + 16 * j];
        float4 a0 = *reinterpret_cast<const float4*>(&As[k][ty << 3]);
        float4 a1 = *reinterpret_cast<const float4*>(&As[k][(ty << 3) + 4]);
        float av[8] = {a0.x, a0.y, a0.z, a0.w, a1.x, a1.y, a1.z, a1.w};
        #pragma unroll
        for (int i = 0; i < 8; i++)
            #pragma unroll
            for (int j = 0; j < 5; j++)
                acc[i][j] = fmaf(av[i], wv[j], acc[i][j]);
    }

    #pragma unroll
    for (int j = 0; j < 5; j++) {
        int c = tx + 16 * j;
        float bv = (c < 64) ? bc1[c] : 0.f;
        #pragma unroll
        for (int i = 0; i < 8; i++) {
            int r = m0 + (ty << 3) + i;
            float v = acc[i][j] + bv;
            if (c < 64) g_preh[(size_t)r * 64 + c]        = __float2half_rn(v);
            else        g_igh [(size_t)r * 16 + (c - 64)] = __float2half_rn(v);
        }
    }
}

// ---------------------------------------------------------------------------
// Fused persistent step kernel. Each WARP owns 4 batch rows end-to-end:
//   Phase A: acc2[4 rows][4 colblocks] = h @ [Wc1h | Whh(r,z,n)]  (f32x2, regs)
//   Phase B: attention per row — hproj comes straight from acc2[i][0]
//   Phase C: GRU — gh gates come straight from acc2[i][1..3]
// No __syncthreads in the loop; h rows are warp-private in smem.
// ---------------------------------------------------------------------------
// Dynamic smem layout (float offsets):
#define SW_OFF    0            // [64][256] combined W      16384
#define SH_OFF    16384        // [32][66]  h (padded)       2112
#define SWIH_OFF  18496        // [16][192] Wih              3072
#define SBIH_OFF  21568        // [192] bih
#define SBHH_OFF  21760        // [192] bhh
#define SWO_OFF   21952        // [128] Wo
#define SWC2_OFF  22080        // [64]  Wc2
#define SWEY_OFF  22144        // [32]  We rows 64,65
#define SBE_OFF   22176        // [16]  be
#define SBO_OFF   22192        // [2]   bo
#define SMEM_FLOATS 22196
#define SMEM_BYTES  (SMEM_FLOATS * 4)

__global__ void __launch_bounds__(256, 2)
step_kernel(const float* __restrict__ lastx,
            const float* __restrict__ zo,
            const float* __restrict__ Wc1,
            const float* __restrict__ Whh,
            const float* __restrict__ bhh,
            const float* __restrict__ Wih,
            const float* __restrict__ bih,
            const float* __restrict__ Wc2,
            const float* __restrict__ We,
            const float* __restrict__ be,
            const float* __restrict__ Wo,
            const float* __restrict__ bo,
            float* __restrict__ out,
            int B, int pred_len)
{
    extern __shared__ float sm[];
    float* sW   = sm + SW_OFF;
    float* sh   = sm + SH_OFF;
    float* sWih = sm + SWIH_OFF;
    float* sbih = sm + SBIH_OFF;
    float* sbhh = sm + SBHH_OFF;
    float* sWo  = sm + SWO_OFF;
    float* sWc2 = sm + SWC2_OFF;
    float* sWeY = sm + SWEY_OFF;
    float* sbe  = sm + SBE_OFF;
    float* sbo  = sm + SBO_OFF;

    const int tid  = threadIdx.x;
    const int lane = tid & 31;
    const int wrp  = tid >> 5;
    const int b0   = blockIdx.x * BPB;

    // ---- init: weights + h ----
    for (int i = tid; i < 64 * 256; i += 256) {
        int k = i >> 8, c = i & 255;
        sW[i] = (c < 64) ? Wc1[(64 + k) * 64 + c] : Whh[k * 192 + (c - 64)];
    }
    for (int i = tid; i < 16 * 192; i += 256) sWih[i] = Wih[i];
    if (tid < 192) { sbih[tid] = bih[tid]; sbhh[tid] = bhh[tid]; }
    if (tid < 128) sWo[tid]  = Wo[tid];
    if (tid < 64)  sWc2[tid] = Wc2[tid];
    if (tid < 32)  sWeY[tid] = We[64 * 16 + tid];
    if (tid < 16)  sbe[tid]  = be[tid];
    if (tid < 2)   sbo[tid]  = bo[tid];
    for (int i = tid; i < BPB * 64; i += 256) {
        int r = i >> 6, k = i & 63;
        sh[r * 66 + k] = zo[(size_t)(b0 + r) * 64 + k];
    }
    __syncthreads();

    // ---- hoisted per-lane constants ----
    const int   c2   = 2 * lane;
    const float wA   = sWc2[c2];
    const float wB   = sWc2[c2 + 1];
    const float wo0  = sWo[lane * 2],       wo1 = sWo[lane * 2 + 1];
    const float wo2  = sWo[(lane + 32) * 2], wo3 = sWo[(lane + 32) * 2 + 1];
    const float bo0  = sbo[0], bo1 = sbo[1];
    const float biR0 = sbih[c2],       biR1 = sbih[c2 + 1];
    const float biZ0 = sbih[64 + c2],  biZ1 = sbih[64 + c2 + 1];
    const float biN0 = sbih[128 + c2], biN1 = sbih[128 + c2 + 1];
    const float bhR0 = sbhh[c2],       bhR1 = sbhh[c2 + 1];
    const float bhZ0 = sbhh[64 + c2],  bhZ1 = sbhh[64 + c2 + 1];
    const float bhN0 = sbhh[128 + c2], bhN1 = sbhh[128 + c2 + 1];
    const float weY0 = (lane < 16) ? sWeY[lane] : 0.f;
    const float weY1 = (lane < 16) ? sWeY[16 + lane] : 0.f;
    const float bev  = (lane < 16) ? sbe[lane] : 0.f;

    const __half2* preh2 = reinterpret_cast<const __half2*>(g_preh);

    for (int t = 0; t < pred_len; t++) {
        // ============ Phase A: acc2 = h(4 rows) @ W256 (raw, no bias) ========
        ull acc2[4][4];
        #pragma unroll
        for (int i = 0; i < 4; i++)
            #pragma unroll
            for (int j = 0; j < 4; j++) acc2[i][j] = 0ull;

        #pragma unroll 4
        for (int k = 0; k < 64; k++) {
            ull wv[4];
            #pragma unroll
            for (int j = 0; j < 4; j++)
                wv[j] = *reinterpret_cast<const ull*>(&sW[k * 256 + c2 + 64 * j]);
            #pragma unroll
            for (int i = 0; i < 4; i++) {
                ull h2 = pack2(sh[(4 * wrp + i) * 66 + k]);
                #pragma unroll
                for (int j = 0; j < 4; j++)
                    asm("fma.rn.f32x2 %0, %1, %2, %0;"
                        : "+l"(acc2[i][j]) : "l"(h2), "l"(wv[j]));
            }
        }

        // ============ Phases B+C per owned row ============
        #pragma unroll 1
        for (int i = 0; i < 4; i++) {
            const int bl = 4 * wrp + i;
            const int bg = b0 + bl;

            // ---- y ----
            float y0, y1;
            if (t == 0) {
                y0 = lastx[2 * bg];
                y1 = lastx[2 * bg + 1];
            } else {
                float h0 = sh[bl * 66 + lane];
                float h1 = sh[bl * 66 + 32 + lane];
                float s0 = h0 * wo0 + h1 * wo2;
                float s1 = h0 * wo1 + h1 * wo3;
                #pragma unroll
                for (int m = 16; m > 0; m >>= 1) {
                    s0 += __shfl_xor_sync(0xffffffffu, s0, m);
                    s1 += __shfl_xor_sync(0xffffffffu, s1, m);
                }
                y0 = s0 + bo0;
                y1 = s1 + bo1;
                if (lane == 0) {
                    out[((size_t)(t - 1) * B + bg) * 2 + 0] = y0;
                    out[((size_t)(t - 1) * B + bg) * 2 + 1] = y1;
                }
            }

            // ---- attention scores ----
            const float2 hp = unpack2(acc2[i][0]);   // hproj[b][2lane,2lane+1]
            float cn[ND];
            #pragma unroll
            for (int n = 0; n < ND; n++) {
                float2 p = __half22float2(preh2[(((size_t)n * B + bg) << 5) + lane]);
                float c = tanh_hw(p.x + hp.x) * wA + tanh_hw(p.y + hp.y) * wB;
                #pragma unroll
                for (int m = 16; m > 0; m >>= 1)
                    c += __shfl_xor_sync(0xffffffffu, c, m);
                cn[n] = c;
            }

            // ---- softmax over 20 dests (all lanes hold full sums) ----
            float mx = cn[0];
            #pragma unroll
            for (int n = 1; n < ND; n++) mx = fmaxf(mx, cn[n]);
            float s = 0.f;
            #pragma unroll
            for (int n = 0; n < ND; n++) { cn[n] = __expf(cn[n] - mx); s += cn[n]; }
            const float inv = 1.f / s;

            // ---- weighted ig + embedding (lane<16 holds emb[lane]) ----
            float embv = 0.f;
            if (lane < 16) {
                float wa = 0.f;
                #pragma unroll
                for (int n = 0; n < ND; n++)
                    wa = fmaf(cn[n],
                              __half2float(g_igh[(((size_t)n * B + bg) << 4) + lane]),
                              wa);
                wa *= inv;
                embv = wa + y0 * weY0 + y1 * weY1 + bev;
            }

            // ---- GRU: gi = emb @ Wih (f32x2), gates from acc2[i][1..3] ----
            ull aR = 0ull, aZ = 0ull, aN = 0ull;
            #pragma unroll
            for (int k = 0; k < 16; k++) {
                float e = __shfl_sync(0xffffffffu, embv, k);
                ull e2 = pack2(e);
                ull wr_ = *reinterpret_cast<const ull*>(&sWih[k * 192 + c2]);
                ull wz_ = *reinterpret_cast<const ull*>(&sWih[k * 192 + 64 + c2]);
                ull wn_ = *reinterpret_cast<const ull*>(&sWih[k * 192 + 128 + c2]);
                asm("fma.rn.f32x2 %0, %1, %2, %0;" : "+l"(aR) : "l"(e2), "l"(wr_));
                asm("fma.rn.f32x2 %0, %1, %2, %0;" : "+l"(aZ) : "l"(e2), "l"(wz_));
                asm("fma.rn.f32x2 %0, %1, %2, %0;" : "+l"(aN) : "l"(e2), "l"(wn_));
            }
            float2 gR = unpack2(aR), gZ = unpack2(aZ), gN = unpack2(aN);
            float2 hR = unpack2(acc2[i][1]);
            float2 hZ = unpack2(acc2[i][2]);
            float2 hN = unpack2(acc2[i][3]);

            float r0 = sigmoidf_(gR.x + biR0 + hR.x + bhR0);
            float r1 = sigmoidf_(gR.y + biR1 + hR.y + bhR1);
            float z0 = sigmoidf_(gZ.x + biZ0 + hZ.x + bhZ0);
            float z1 = sigmoidf_(gZ.y + biZ1 + hZ.y + bhZ1);
            float n0 = tanhf(gN.x + biN0 + r0 * (hN.x + bhN0));
            float n1 = tanhf(gN.y + biN1 + r1 * (hN.y + bhN1));

            float ho0 = sh[bl * 66 + c2];
            float ho1 = sh[bl * 66 + c2 + 1];
            __syncwarp();   // all reads of this row's old h complete before write
            sh[bl * 66 + c2]     = (1.f - z0) * n0 + z0 * ho0;
            sh[bl * 66 + c2 + 1] = (1.f - z1) * n1 + z1 * ho1;
        }
        __syncwarp();       // h rows updated before next step's Phase A reads
    }

    // ---- final output row: ys[pred_len-1] = h @ Wo + bo ----
    #pragma unroll 1
    for (int i = 0; i < 4; i++) {
        const int bl = 4 * wrp + i;
        const int bg = b0 + bl;
        float h0 = sh[bl * 66 + lane];
        float h1 = sh[bl * 66 + 32 + lane];
        float s0 = h0 * wo0 + h1 * wo2;
        float s1 = h0 * wo1 + h1 * wo3;
        #pragma unroll
        for (int m = 16; m > 0; m >>= 1) {
            s0 += __shfl_xor_sync(0xffffffffu, s0, m);
            s1 += __shfl_xor_sync(0xffffffffu, s1, m);
        }
        if (lane == 0) {
            out[((size_t)(pred_len - 1) * B + bg) * 2 + 0] = s0 + bo0;
            out[((size_t)(pred_len - 1) * B + bg) * 2 + 1] = s1 + bo1;
        }
    }
}

// ---------------------------------------------------------------------------
// Host launcher: 2 kernels total.
// ---------------------------------------------------------------------------
extern "C" void kernel_launch(void* const* d_in, const int* in_sizes, int n_in,
                              void* d_out, int out_size)
{
    const int o = (in_sizes[0] == 1) ? 1 : 0;

    const float* lastx = (const float*)d_in[o + 0];
    const float* zo    = (const float*)d_in[o + 1];
    const float* inter = (const float*)d_in[o + 3];
    const float* We    = (const float*)d_in[o + 4];
    const float* be    = (const float*)d_in[o + 5];
    const float* Wih   = (const float*)d_in[o + 6];
    const float* Whh   = (const float*)d_in[o + 7];
    const float* bih   = (const float*)d_in[o + 8];
    const float* bhh   = (const float*)d_in[o + 9];
    const float* Wc1   = (const float*)d_in[o + 10];
    const float* bc1   = (const float*)d_in[o + 11];
    const float* Wc2   = (const float*)d_in[o + 12];
    const float* Wo    = (const float*)d_in[o + 14];
    const float* bo    = (const float*)d_in[o + 15];
    float* out = (float*)d_out;

    const int B = in_sizes[o + 0] / 2;
    const int pred_len = out_size / (2 * B);
    (void)n_in;

    static bool attr_done = false;
    if (!attr_done) {
        cudaFuncSetAttribute(step_kernel,
                             cudaFuncAttributeMaxDynamicSharedMemorySize,
                             SMEM_BYTES);
        attr_done = true;
    }

    // Precompute pre (fp16) + ig (fp16) in one pass over intermediate.
    precomp_kernel<<<(ND * B) / 64, 128>>>(inter, Wc1, bc1, We);

    // One persistent kernel for the whole recurrence.
    step_kernel<<<B / BPB, 256, SMEM_BYTES>>>(lastx, zo, Wc1, Whh, bhh,
                                              Wih, bih, Wc2, We, be, Wo, bo,
                                              out, B, pred_len);
}